// round 15
// baseline (speedup 1.0000x reference)
#include <cuda_runtime.h>
#include <cuda_fp16.h>

#define Bb   2
#define Ss   1024
#define Hh   768
#define Dd   24
#define Kk   96
#define VIN  2304
#define VHID 768

// ---------------- scratch ----------------
__device__ float g_Zj[Bb * Ss * Dd];
__device__ float g_Zi[Bb * Ss * Dd];
__device__ float g_CJ[Bb * Ss * Kk];
__device__ float g_CI[Bb * Ss * Kk];
__device__ float g_probs[(size_t)Bb * Ss * Ss];
__device__ float g_ctx[Bb * Ss * Hh];
__device__ float g_ctxh[Bb * Ss * Hh];
__device__ float g_hid[Bb * Ss * VHID];

__device__ __forceinline__ unsigned pack_h2(float lo, float hi) {
    __half2 h = __floats2half2_rn(lo, hi);   // .x = lo half (low 16 bits)
    return *(unsigned*)&h;
}
// fp16 m16n8k16, f32 accumulate
__device__ __forceinline__ void mma_f16(float& d0, float& d1, float& d2, float& d3,
                                        unsigned a0, unsigned a1, unsigned a2, unsigned a3,
                                        unsigned b0, unsigned b1) {
    asm volatile(
        "mma.sync.aligned.m16n8k16.row.col.f32.f16.f16.f32 "
        "{%0,%1,%2,%3}, {%4,%5,%6,%7}, {%8,%9}, {%0,%1,%2,%3};"
        : "+f"(d0), "+f"(d1), "+f"(d2), "+f"(d3)
        : "r"(a0), "r"(a1), "r"(a2), "r"(a3), "r"(b0), "r"(b1));
}

// ================= K1: Zj, Zi, cj = b1 + Zj@W1a, ci = Zi@W1b =================
__global__ __launch_bounds__(128) void k1_prep(const float* __restrict__ Hj,
                                               const float* __restrict__ Hi,
                                               const float* __restrict__ Wpj,
                                               const float* __restrict__ Wpi,
                                               const float* __restrict__ W1,
                                               const float* __restrict__ b1) {
    int bs  = blockIdx.x;
    int tid = threadIdx.x;
    int w   = tid >> 5, l = tid & 31;
    __shared__ float part[4][Dd];
    __shared__ float zjs[Dd], zis[Dd];

    const float* Hrow = (w < 2 ? Hj : Hi) + (size_t)bs * Hh;
    const float* Wp   = (w < 2 ? Wpj : Wpi);
    if (l < Dd) {
        float acc = 0.f;
        int h0 = (w & 1) * (Hh / 2);
#pragma unroll 4
        for (int h = h0; h < h0 + Hh / 2; ++h)
            acc = fmaf(Hrow[h], Wp[h * Dd + l], acc);
        part[w][l] = acc;
    }
    __syncthreads();
    if (tid < Dd) {
        float z = part[0][tid] + part[1][tid];
        zjs[tid] = z;
        g_Zj[bs * Dd + tid] = z;
    }
    if (tid >= 32 && tid < 32 + Dd) {
        int d = tid - 32;
        float z = part[2][d] + part[3][d];
        zis[d] = z;
        g_Zi[bs * Dd + d] = z;
    }
    __syncthreads();
    if (tid < Kk) {
        float cj = b1[tid], ci = 0.f;
#pragma unroll
        for (int d = 0; d < Dd; ++d) {
            cj = fmaf(zjs[d], W1[d * Kk + tid], cj);
            ci = fmaf(zis[d], W1[(Dd + d) * Kk + tid], ci);
        }
        g_CJ[bs * Kk + tid] = cj;
        g_CI[bs * Kk + tid] = ci;
    }
}

// ================= K2 (fp16 tensor-core): logits + softmax per s-row =================
// Same structure as R10 k2; operands f16-paired along K (u32 = 2 halves).
// K = 48 -> 3 m16n8k16 chunks (was 6 m16n8k8).
__global__ __launch_bounds__(256) void k2_mma(const float* __restrict__ W1,
                                              const float* __restrict__ W2,
                                              const float* __restrict__ mask) {
    const int bs  = blockIdx.x;
    const int b   = bs >> 10;
    const int tid = threadIdx.x;
    const int warp = tid >> 5, lane = tid & 31;
    const int g  = lane >> 2, t4 = lane & 3;
    const int wm = warp & 1;
    const int wn = warp >> 1;

    __shared__ unsigned Ws16[24][104];  // k-pairs x 96 cols (pad 104: t4*104+g mod 32 distinct)
    __shared__ unsigned Fs16[64][28];   // 64 rows x 24 k-pairs (pad 28: g*28+t4 mod 32 distinct)
    __shared__ float cjw[Kk], w2s[Kk], zjs[Dd];
    __shared__ float lg[Ss];
    __shared__ float lgpart[4][64];
    __shared__ float red[8];

    // weights Wcd[d][k]: d<24 -> W1c row (2Dd+d), else W1d row (3Dd+d-24); pack d-pairs.
    for (int idx = tid; idx < 24 * Kk; idx += 256) {
        int p = idx / Kk, n = idx - p * Kk;
        int d0 = 2 * p, d1 = 2 * p + 1;
        float v0 = (d0 < Dd) ? W1[(2 * Dd + d0) * Kk + n] : W1[(3 * Dd + (d0 - Dd)) * Kk + n];
        float v1 = (d1 < Dd) ? W1[(2 * Dd + d1) * Kk + n] : W1[(3 * Dd + (d1 - Dd)) * Kk + n];
        Ws16[p][n] = pack_h2(v0, v1);
    }
    if (tid < Kk) {
        cjw[tid] = g_CJ[(size_t)bs * Kk + tid];
        w2s[tid] = W2[tid];
    }
    if (tid < Dd) zjs[tid] = g_Zj[(size_t)bs * Dd + tid];
    __syncthreads();

    float zj[Dd];
#pragma unroll
    for (int d = 0; d < Dd; ++d) zj[d] = zjs[d];

    const float* ciBase = g_CI + (size_t)b * Ss * Kk;
    const float* ziBase = g_Zi + (size_t)b * Ss * Dd;

#pragma unroll 1
    for (int sub = 0; sub < 16; ++sub) {
        const int t0 = sub * 64;

        // ---- features (packed f16 pairs along k) ----
        {
            const int r = tid >> 2, p = tid & 3;
            const int t = t0 + r;
            const int half = p & 1;
            const float* zr = ziBase + (size_t)t * Dd + half * 12;
            float zi[12];
#pragma unroll
            for (int q = 0; q < 3; ++q) {
                float4 v = *(const float4*)(zr + 4 * q);
                zi[4 * q] = v.x; zi[4 * q + 1] = v.y; zi[4 * q + 2] = v.z; zi[4 * q + 3] = v.w;
            }
            const int base2 = half * 6 + ((p >= 2) ? 12 : 0);  // u32 offset
            if (p < 2) {
#pragma unroll
                for (int j2 = 0; j2 < 6; ++j2) {
                    float v0 = zj[half * 12 + 2 * j2] * zi[2 * j2];
                    float v1 = zj[half * 12 + 2 * j2 + 1] * zi[2 * j2 + 1];
                    Fs16[r][base2 + j2] = pack_h2(v0, v1);
                }
            } else {
#pragma unroll
                for (int j2 = 0; j2 < 6; ++j2) {
                    float v0 = fabsf(zj[half * 12 + 2 * j2] - zi[2 * j2]);
                    float v1 = fabsf(zj[half * 12 + 2 * j2 + 1] - zi[2 * j2 + 1]);
                    Fs16[r][base2 + j2] = pack_h2(v0, v1);
                }
            }
        }
        __syncthreads();

        // ---- acc init with ci + cj (C frag layout unchanged) ----
        float acc[2][3][4];
#pragma unroll
        for (int mt = 0; mt < 2; ++mt) {
            int r0 = wm * 32 + mt * 16 + g;
            int r1 = r0 + 8;
#pragma unroll
            for (int nt = 0; nt < 3; ++nt) {
                int c = wn * 24 + nt * 8 + 2 * t4;
                float2 ci0 = *(const float2*)(ciBase + (size_t)(t0 + r0) * Kk + c);
                float2 ci1 = *(const float2*)(ciBase + (size_t)(t0 + r1) * Kk + c);
                acc[mt][nt][0] = ci0.x + cjw[c];
                acc[mt][nt][1] = ci0.y + cjw[c + 1];
                acc[mt][nt][2] = ci1.x + cjw[c];
                acc[mt][nt][3] = ci1.y + cjw[c + 1];
            }
        }

        // ---- mma: 3 k16-chunks ----
#pragma unroll
        for (int cc = 0; cc < 3; ++cc) {
            const int kb = cc * 8;  // u32 (k-pair) base
            unsigned afr[2][4], bfr[3][2];
#pragma unroll
            for (int mt = 0; mt < 2; ++mt) {
                int rb = wm * 32 + mt * 16 + g;
                afr[mt][0] = Fs16[rb][kb + t4];
                afr[mt][1] = Fs16[rb + 8][kb + t4];
                afr[mt][2] = Fs16[rb][kb + t4 + 4];
                afr[mt][3] = Fs16[rb + 8][kb + t4 + 4];
            }
#pragma unroll
            for (int nt = 0; nt < 3; ++nt) {
                int cb = wn * 24 + nt * 8 + g;
                bfr[nt][0] = Ws16[kb + t4][cb];
                bfr[nt][1] = Ws16[kb + t4 + 4][cb];
            }
#pragma unroll
            for (int mt = 0; mt < 2; ++mt)
#pragma unroll
                for (int nt = 0; nt < 3; ++nt)
                    mma_f16(acc[mt][nt][0], acc[mt][nt][1], acc[mt][nt][2], acc[mt][nt][3],
                            afr[mt][0], afr[mt][1], afr[mt][2], afr[mt][3],
                            bfr[nt][0], bfr[nt][1]);
        }

        // ---- epilogue: relu + w2-dot, reduce over t4 then wn ----
#pragma unroll
        for (int mt = 0; mt < 2; ++mt) {
            float p0 = 0.f, p1 = 0.f;
#pragma unroll
            for (int nt = 0; nt < 3; ++nt) {
                int c = wn * 24 + nt * 8 + 2 * t4;
                float wa = w2s[c], wb = w2s[c + 1];
                p0 = fmaf(fmaxf(acc[mt][nt][0], 0.f), wa, p0);
                p0 = fmaf(fmaxf(acc[mt][nt][1], 0.f), wb, p0);
                p1 = fmaf(fmaxf(acc[mt][nt][2], 0.f), wa, p1);
                p1 = fmaf(fmaxf(acc[mt][nt][3], 0.f), wb, p1);
            }
            p0 += __shfl_xor_sync(0xffffffffu, p0, 1);
            p0 += __shfl_xor_sync(0xffffffffu, p0, 2);
            p1 += __shfl_xor_sync(0xffffffffu, p1, 1);
            p1 += __shfl_xor_sync(0xffffffffu, p1, 2);
            if (t4 == 0) {
                lgpart[wn][wm * 32 + mt * 16 + g]     = p0;
                lgpart[wn][wm * 32 + mt * 16 + g + 8] = p1;
            }
        }
        __syncthreads();
        if (tid < 64) {
            float v = (lgpart[0][tid] + lgpart[1][tid]) + (lgpart[2][tid] + lgpart[3][tid]);
            int t = t0 + tid;
            float m = mask[b * Ss + t];
            lg[t] = v + (1.0f - m) * (-3.402823466e38f);
        }
        __syncthreads();
    }

    // ---- softmax (b2 constant -> cancels) ----
    float mx = -3.402823466e38f;
    for (int i = tid; i < Ss; i += 256) mx = fmaxf(mx, lg[i]);
#pragma unroll
    for (int o = 16; o; o >>= 1) mx = fmaxf(mx, __shfl_xor_sync(0xffffffffu, mx, o));
    if (lane == 0) red[warp] = mx;
    __syncthreads();
    mx = red[0];
#pragma unroll
    for (int w2i = 1; w2i < 8; ++w2i) mx = fmaxf(mx, red[w2i]);
    __syncthreads();

    float sum = 0.f;
    for (int i = tid; i < Ss; i += 256) {
        float e = __expf(lg[i] - mx);
        lg[i] = e;
        sum += e;
    }
#pragma unroll
    for (int o = 16; o; o >>= 1) sum += __shfl_xor_sync(0xffffffffu, sum, o);
    if (lane == 0) red[warp] = sum;
    __syncthreads();
    sum = 0.f;
#pragma unroll
    for (int w2i = 0; w2i < 8; ++w2i) sum += red[w2i];
    float inv = 1.0f / sum;

    float* orow = g_probs + (size_t)bs * Ss;
    for (int i = tid; i < Ss; i += 256) orow[i] = lg[i] * inv;
}

// ====== fp16 GEMM: 128x96 tile, k-slab 32 floats (16 u32 pairs), 2-slab-deep pipeline ======
// MODE 0: ctx = probs @ H_i (per b); epilogue also writes ctxh = ctx * Hj
// MODE 1: hid = relu([ctx|Hj|ctxh] @ Wv1 + bv1)
// MODE 2: out = alpha * (hid @ Wv2 + bv2)
template <int MODE>
__global__ __launch_bounds__(256) void gemm_mma(const float* __restrict__ Ap,
                                                const float* __restrict__ Bp,
                                                const float* __restrict__ Hjp,
                                                const float* __restrict__ bias,
                                                const float* __restrict__ alpha,
                                                float* __restrict__ Cp, int Kdim, int lda) {
    const int m0 = blockIdx.x * 128;
    const int n0 = blockIdx.y * 96;
    const float* A = Ap;
    const float* Bm = Bp;
    float* C = Cp;
    size_t rowbase = 0;
    if (MODE == 0) {
        int b = blockIdx.z;
        A += (size_t)b * Ss * Ss;
        Bm += (size_t)b * Ss * Hh;
        C += (size_t)b * Ss * Hh;
        rowbase = (size_t)b * Ss;
    }

    // As16[row][kp]: 16 k-pairs (32 k) per slab; pad 20 (frag g*20+t4 mod 32 distinct)
    __shared__ unsigned As16[2][128][20];
    // Bs16[kp][n]: pad 104 (frag t4*104+g mod 32 distinct)
    __shared__ unsigned Bs16[2][16][104];

    const int tid  = threadIdx.x;
    const int warp = tid >> 5, lane = tid & 31;
    const int g  = lane >> 2, t4 = lane & 3;
    const int wm = warp & 3;
    const int wn = warp >> 2;

    // A: 2 threads per row, each 16 consecutive k-floats (4 float4) -> 8 u32
    const int ar = tid >> 1, acq = (tid & 1) * 16, au = (tid & 1) * 8;
    // B: pair-row groups: 16 kp x 24 col-groups = 384; idx = tid (+256 for tid<128)
    const int b0r = tid / 24, b0c = (tid % 24) * 4;
    const int i1  = tid + 256;
    const int b1r = i1 / 24, b1c = (i1 % 24) * 4;
    const bool hasB1 = (tid < 128);

    float acc[2][6][4];
#pragma unroll
    for (int mt = 0; mt < 2; ++mt)
#pragma unroll
        for (int nt = 0; nt < 6; ++nt)
#pragma unroll
            for (int v = 0; v < 4; ++v) acc[mt][nt][v] = 0.f;

    const int nkt = Kdim / 32;   // 32 / 72 / 24 — always even

    struct Regs {
        float4 a[4];
        float4 b0lo, b0hi, b1lo, b1hi;   // pair rows (2r, 2r+1) for groups 0,1
    };

    auto loadABv = [&](Regs& R, int k0) {
        int kc = k0 + acq;
        if (MODE == 1) {
            int seg = kc / Hh;   // slab-uniform (Hh % 32 == 0)
            const float* base = (seg == 0) ? g_ctx : (seg == 1) ? Hjp : g_ctxh;
            int kq = kc - seg * Hh;
            const float* rp = base + (size_t)(m0 + ar) * Hh + kq;
#pragma unroll
            for (int q = 0; q < 4; ++q) R.a[q] = *(const float4*)(rp + 4 * q);
        } else {
            const float* rp = A + (size_t)(m0 + ar) * lda + kc;
#pragma unroll
            for (int q = 0; q < 4; ++q) R.a[q] = *(const float4*)(rp + 4 * q);
        }
        R.b0lo = *(const float4*)(Bm + (size_t)(k0 + 2 * b0r) * Hh + n0 + b0c);
        R.b0hi = *(const float4*)(Bm + (size_t)(k0 + 2 * b0r + 1) * Hh + n0 + b0c);
        if (hasB1) {
            R.b1lo = *(const float4*)(Bm + (size_t)(k0 + 2 * b1r) * Hh + n0 + b1c);
            R.b1hi = *(const float4*)(Bm + (size_t)(k0 + 2 * b1r + 1) * Hh + n0 + b1c);
        }
    };

    auto storeABv = [&](const Regs& R, int buf) {
        float va[16];
#pragma unroll
        for (int q = 0; q < 4; ++q) {
            va[4 * q]     = R.a[q].x;
            va[4 * q + 1] = R.a[q].y;
            va[4 * q + 2] = R.a[q].z;
            va[4 * q + 3] = R.a[q].w;
        }
#pragma unroll
        for (int j = 0; j < 8; ++j)
            As16[buf][ar][au + j] = pack_h2(va[2 * j], va[2 * j + 1]);
        {
            const float lo[4] = {R.b0lo.x, R.b0lo.y, R.b0lo.z, R.b0lo.w};
            const float hi[4] = {R.b0hi.x, R.b0hi.y, R.b0hi.z, R.b0hi.w};
#pragma unroll
            for (int j = 0; j < 4; ++j) Bs16[buf][b0r][b0c + j] = pack_h2(lo[j], hi[j]);
        }
        if (hasB1) {
            const float lo[4] = {R.b1lo.x, R.b1lo.y, R.b1lo.z, R.b1lo.w};
            const float hi[4] = {R.b1hi.x, R.b1hi.y, R.b1hi.z, R.b1hi.w};
#pragma unroll
            for (int j = 0; j < 4; ++j) Bs16[buf][b1r][b1c + j] = pack_h2(lo[j], hi[j]);
        }
    };

    auto mmaStep = [&](int cur) {
#pragma unroll
        for (int cc = 0; cc < 2; ++cc) {     // 2 k16-chunks per 32-k slab
            const int kb = cc * 8;
            unsigned afr[2][4], bfr[6][2];
#pragma unroll
            for (int mt = 0; mt < 2; ++mt) {
                int rb = wm * 32 + mt * 16 + g;
                afr[mt][0] = As16[cur][rb][kb + t4];
                afr[mt][1] = As16[cur][rb + 8][kb + t4];
                afr[mt][2] = As16[cur][rb][kb + t4 + 4];
                afr[mt][3] = As16[cur][rb + 8][kb + t4 + 4];
            }
#pragma unroll
            for (int nt = 0; nt < 6; ++nt) {
                int cb = wn * 48 + nt * 8 + g;
                bfr[nt][0] = Bs16[cur][kb + t4][cb];
                bfr[nt][1] = Bs16[cur][kb + t4 + 4][cb];
            }
#pragma unroll
            for (int mt = 0; mt < 2; ++mt)
#pragma unroll
                for (int nt = 0; nt < 6; ++nt)
                    mma_f16(acc[mt][nt][0], acc[mt][nt][1], acc[mt][nt][2], acc[mt][nt][3],
                            afr[mt][0], afr[mt][1], afr[mt][2], afr[mt][3],
                            bfr[nt][0], bfr[nt][1]);
        }
    };

    Regs R0, R1;
    loadABv(R0, 0);
    loadABv(R1, 32);
    storeABv(R0, 0);
    __syncthreads();

#pragma unroll 1
    for (int kt = 0; kt < nkt; kt += 2) {
        if (kt + 1 < nkt) storeABv(R1, 1);
        if (kt + 2 < nkt) loadABv(R0, (kt + 2) * 32);
        mmaStep(0);
        if (kt + 1 < nkt) __syncthreads();
        if (kt + 1 < nkt) {
            if (kt + 2 < nkt) storeABv(R0, 0);
            if (kt + 3 < nkt) loadABv(R1, (kt + 3) * 32);
            mmaStep(1);
            if (kt + 2 < nkt) __syncthreads();
        }
    }

    // ---------------- epilogue ----------------
    const float al = (MODE == 2) ? alpha[0] : 0.f;
#pragma unroll
    for (int mt = 0; mt < 2; ++mt) {
        int r0 = m0 + wm * 32 + mt * 16 + g;
        int r1 = r0 + 8;
#pragma unroll
        for (int nt = 0; nt < 6; ++nt) {
            int c0 = n0 + wn * 48 + nt * 8 + 2 * t4;
            float v00 = acc[mt][nt][0], v01 = acc[mt][nt][1];
            float v10 = acc[mt][nt][2], v11 = acc[mt][nt][3];
            if (MODE == 0) {
                *(float2*)(&C[(size_t)r0 * Hh + c0]) = make_float2(v00, v01);
                *(float2*)(&C[(size_t)r1 * Hh + c0]) = make_float2(v10, v11);
                size_t g0 = rowbase + r0, g1 = rowbase + r1;
                float2 h0 = *(const float2*)(Hjp + g0 * Hh + c0);
                float2 h1 = *(const float2*)(Hjp + g1 * Hh + c0);
                *(float2*)(&g_ctxh[g0 * Hh + c0]) = make_float2(v00 * h0.x, v01 * h0.y);
                *(float2*)(&g_ctxh[g1 * Hh + c0]) = make_float2(v10 * h1.x, v11 * h1.y);
            } else if (MODE == 1) {
                float2 bsv = *(const float2*)(&bias[c0]);
                *(float2*)(&C[(size_t)r0 * VHID + c0]) =
                    make_float2(fmaxf(v00 + bsv.x, 0.f), fmaxf(v01 + bsv.y, 0.f));
                *(float2*)(&C[(size_t)r1 * VHID + c0]) =
                    make_float2(fmaxf(v10 + bsv.x, 0.f), fmaxf(v11 + bsv.y, 0.f));
            } else {
                float2 bsv = *(const float2*)(&bias[c0]);
                *(float2*)(&C[(size_t)r0 * Hh + c0]) =
                    make_float2(al * (v00 + bsv.x), al * (v01 + bsv.y));
                *(float2*)(&C[(size_t)r1 * Hh + c0]) =
                    make_float2(al * (v10 + bsv.x), al * (v11 + bsv.y));
            }
        }
    }
}

// ================= launch =================
extern "C" void kernel_launch(void* const* d_in, const int* in_sizes, int n_in, void* d_out,
                              int out_size) {
    const float* Hj   = (const float*)d_in[0];
    const float* Hi   = (const float*)d_in[1];
    const float* mask = (const float*)d_in[2];
    const float* Wpj  = (const float*)d_in[3];
    const float* Wpi  = (const float*)d_in[4];
    const float* W1   = (const float*)d_in[5];
    const float* b1   = (const float*)d_in[6];
    const float* W2   = (const float*)d_in[7];
    // d_in[8] = b2: constant logit shift -> cancels in softmax
    const float* Wv1   = (const float*)d_in[9];
    const float* bv1   = (const float*)d_in[10];
    const float* Wv2   = (const float*)d_in[11];
    const float* bv2   = (const float*)d_in[12];
    const float* alpha = (const float*)d_in[13];
    float* out = (float*)d_out;

    float* d_probs = nullptr;
    float* d_ctx = nullptr;
    float* d_hid = nullptr;
    cudaGetSymbolAddress((void**)&d_probs, g_probs);
    cudaGetSymbolAddress((void**)&d_ctx, g_ctx);
    cudaGetSymbolAddress((void**)&d_hid, g_hid);

    k1_prep<<<Bb * Ss, 128>>>(Hj, Hi, Wpj, Wpi, W1, b1);
    k2_mma<<<Bb * Ss, 256>>>(W1, W2, mask);
    gemm_mma<0><<<dim3(Ss / 128, Hh / 96, Bb), 256>>>(d_probs, Hi, Hj, nullptr, nullptr,
                                                      d_ctx, Ss, Ss);
    gemm_mma<1><<<dim3(Bb * Ss / 128, VHID / 96), 256>>>(nullptr, Wv1, Hj, bv1, nullptr, d_hid,
                                                         VIN, 0);
    gemm_mma<2><<<dim3(Bb * Ss / 128, Hh / 96), 256>>>(d_hid, Wv2, nullptr, bv2, alpha, out,
                                                       VHID, VHID);
}

// round 17
// speedup vs baseline: 1.1637x; 1.1637x over previous
#include <cuda_runtime.h>

#define Bb   2
#define Ss   1024
#define Hh   768
#define Dd   24
#define Kk   96
#define VIN  2304
#define VHID 768

// ---------------- scratch ----------------
__device__ float g_Zj[Bb * Ss * Dd];
__device__ float g_Zi[Bb * Ss * Dd];
__device__ float g_CJ[Bb * Ss * Kk];
__device__ float g_CI[Bb * Ss * Kk];
__device__ float g_probs[(size_t)Bb * Ss * Ss];
__device__ float g_ctx[Bb * Ss * Hh];
__device__ float g_ctxh[Bb * Ss * Hh];
__device__ float g_hid[Bb * Ss * VHID];

__device__ __forceinline__ unsigned tf32r(float x) {
    unsigned r;
    asm("cvt.rna.tf32.f32 %0, %1;" : "=r"(r) : "f"(x));
    return r;
}
__device__ __forceinline__ void mma_tf32(float& d0, float& d1, float& d2, float& d3,
                                         unsigned a0, unsigned a1, unsigned a2, unsigned a3,
                                         unsigned b0, unsigned b1) {
    asm volatile(
        "mma.sync.aligned.m16n8k8.row.col.f32.tf32.tf32.f32 "
        "{%0,%1,%2,%3}, {%4,%5,%6,%7}, {%8,%9}, {%0,%1,%2,%3};"
        : "+f"(d0), "+f"(d1), "+f"(d2), "+f"(d3)
        : "r"(a0), "r"(a1), "r"(a2), "r"(a3), "r"(b0), "r"(b1));
}

// ================= K1: Zj, Zi, cj = b1 + Zj@W1a, ci = Zi@W1b =================
__global__ __launch_bounds__(128) void k1_prep(const float* __restrict__ Hj,
                                               const float* __restrict__ Hi,
                                               const float* __restrict__ Wpj,
                                               const float* __restrict__ Wpi,
                                               const float* __restrict__ W1,
                                               const float* __restrict__ b1) {
    int bs  = blockIdx.x;
    int tid = threadIdx.x;
    int w   = tid >> 5, l = tid & 31;
    __shared__ float part[4][Dd];
    __shared__ float zjs[Dd], zis[Dd];

    const float* Hrow = (w < 2 ? Hj : Hi) + (size_t)bs * Hh;
    const float* Wp   = (w < 2 ? Wpj : Wpi);
    if (l < Dd) {
        float acc = 0.f;
        int h0 = (w & 1) * (Hh / 2);
#pragma unroll 4
        for (int h = h0; h < h0 + Hh / 2; ++h)
            acc = fmaf(Hrow[h], Wp[h * Dd + l], acc);
        part[w][l] = acc;
    }
    __syncthreads();
    if (tid < Dd) {
        float z = part[0][tid] + part[1][tid];
        zjs[tid] = z;
        g_Zj[bs * Dd + tid] = z;
    }
    if (tid >= 32 && tid < 32 + Dd) {
        int d = tid - 32;
        float z = part[2][d] + part[3][d];
        zis[d] = z;
        g_Zi[bs * Dd + d] = z;
    }
    __syncthreads();
    if (tid < Kk) {
        float cj = b1[tid], ci = 0.f;
#pragma unroll
        for (int d = 0; d < Dd; ++d) {
            cj = fmaf(zjs[d], W1[d * Kk + tid], cj);
            ci = fmaf(zis[d], W1[(Dd + d) * Kk + tid], ci);
        }
        g_CJ[bs * Kk + tid] = cj;
        g_CI[bs * Kk + tid] = ci;
    }
}

// ================= K2 (tensor-core, tf32, R10/R13 measured-best) =================
__global__ __launch_bounds__(256) void k2_mma(const float* __restrict__ W1,
                                              const float* __restrict__ W2,
                                              const float* __restrict__ mask) {
    const int bs  = blockIdx.x;
    const int b   = bs >> 10;
    const int tid = threadIdx.x;
    const int warp = tid >> 5, lane = tid & 31;
    const int g  = lane >> 2, t4 = lane & 3;
    const int wm = warp & 1;
    const int wn = warp >> 1;

    __shared__ unsigned Ws[48][104];
    __shared__ unsigned Fs[64][52];
    __shared__ float cjw[Kk], w2s[Kk], zjs[Dd];
    __shared__ float lg[Ss];
    __shared__ float lgpart[4][64];
    __shared__ float red[8];

    for (int idx = tid; idx < 48 * Kk; idx += 256) {
        int d = idx / Kk, k = idx - d * Kk;
        float v = (d < Dd) ? W1[(2 * Dd + d) * Kk + k] : W1[(3 * Dd + (d - Dd)) * Kk + k];
        Ws[d][k] = tf32r(v);
    }
    if (tid < Kk) {
        cjw[tid] = g_CJ[(size_t)bs * Kk + tid];
        w2s[tid] = W2[tid];
    }
    if (tid < Dd) zjs[tid] = g_Zj[(size_t)bs * Dd + tid];
    __syncthreads();

    float zj[Dd];
#pragma unroll
    for (int d = 0; d < Dd; ++d) zj[d] = zjs[d];

    const float* ciBase = g_CI + (size_t)b * Ss * Kk;
    const float* ziBase = g_Zi + (size_t)b * Ss * Dd;

#pragma unroll 1
    for (int sub = 0; sub < 16; ++sub) {
        const int t0 = sub * 64;

        {
            const int r = tid >> 2, p = tid & 3;
            const int t = t0 + r;
            const int half = p & 1;
            const float* zr = ziBase + (size_t)t * Dd + half * 12;
            float zi[12];
#pragma unroll
            for (int q = 0; q < 3; ++q) {
                float4 v = *(const float4*)(zr + 4 * q);
                zi[4 * q] = v.x; zi[4 * q + 1] = v.y; zi[4 * q + 2] = v.z; zi[4 * q + 3] = v.w;
            }
            const int base = half * 12 + ((p >= 2) ? 24 : 0);
            if (p < 2) {
#pragma unroll
                for (int j = 0; j < 12; ++j)
                    Fs[r][base + j] = tf32r(zj[half * 12 + j] * zi[j]);
            } else {
#pragma unroll
                for (int j = 0; j < 12; ++j)
                    Fs[r][base + j] = tf32r(fabsf(zj[half * 12 + j] - zi[j]));
            }
        }
        __syncthreads();

        float acc[2][3][4];
#pragma unroll
        for (int mt = 0; mt < 2; ++mt) {
            int r0 = wm * 32 + mt * 16 + g;
            int r1 = r0 + 8;
#pragma unroll
            for (int nt = 0; nt < 3; ++nt) {
                int c = wn * 24 + nt * 8 + 2 * t4;
                float2 ci0 = *(const float2*)(ciBase + (size_t)(t0 + r0) * Kk + c);
                float2 ci1 = *(const float2*)(ciBase + (size_t)(t0 + r1) * Kk + c);
                acc[mt][nt][0] = ci0.x + cjw[c];
                acc[mt][nt][1] = ci0.y + cjw[c + 1];
                acc[mt][nt][2] = ci1.x + cjw[c];
                acc[mt][nt][3] = ci1.y + cjw[c + 1];
            }
        }

#pragma unroll
        for (int k8 = 0; k8 < 48; k8 += 8) {
            unsigned afr[2][4], bfr[3][2];
#pragma unroll
            for (int mt = 0; mt < 2; ++mt) {
                int rb = wm * 32 + mt * 16 + g;
                afr[mt][0] = Fs[rb][k8 + t4];
                afr[mt][1] = Fs[rb + 8][k8 + t4];
                afr[mt][2] = Fs[rb][k8 + t4 + 4];
                afr[mt][3] = Fs[rb + 8][k8 + t4 + 4];
            }
#pragma unroll
            for (int nt = 0; nt < 3; ++nt) {
                int cb = wn * 24 + nt * 8 + g;
                bfr[nt][0] = Ws[k8 + t4][cb];
                bfr[nt][1] = Ws[k8 + t4 + 4][cb];
            }
#pragma unroll
            for (int mt = 0; mt < 2; ++mt)
#pragma unroll
                for (int nt = 0; nt < 3; ++nt)
                    mma_tf32(acc[mt][nt][0], acc[mt][nt][1], acc[mt][nt][2], acc[mt][nt][3],
                             afr[mt][0], afr[mt][1], afr[mt][2], afr[mt][3],
                             bfr[nt][0], bfr[nt][1]);
        }

#pragma unroll
        for (int mt = 0; mt < 2; ++mt) {
            float p0 = 0.f, p1 = 0.f;
#pragma unroll
            for (int nt = 0; nt < 3; ++nt) {
                int c = wn * 24 + nt * 8 + 2 * t4;
                float wa = w2s[c], wb = w2s[c + 1];
                p0 = fmaf(fmaxf(acc[mt][nt][0], 0.f), wa, p0);
                p0 = fmaf(fmaxf(acc[mt][nt][1], 0.f), wb, p0);
                p1 = fmaf(fmaxf(acc[mt][nt][2], 0.f), wa, p1);
                p1 = fmaf(fmaxf(acc[mt][nt][3], 0.f), wb, p1);
            }
            p0 += __shfl_xor_sync(0xffffffffu, p0, 1);
            p0 += __shfl_xor_sync(0xffffffffu, p0, 2);
            p1 += __shfl_xor_sync(0xffffffffu, p1, 1);
            p1 += __shfl_xor_sync(0xffffffffu, p1, 2);
            if (t4 == 0) {
                lgpart[wn][wm * 32 + mt * 16 + g]     = p0;
                lgpart[wn][wm * 32 + mt * 16 + g + 8] = p1;
            }
        }
        __syncthreads();
        if (tid < 64) {
            float v = (lgpart[0][tid] + lgpart[1][tid]) + (lgpart[2][tid] + lgpart[3][tid]);
            int t = t0 + tid;
            float m = mask[b * Ss + t];
            lg[t] = v + (1.0f - m) * (-3.402823466e38f);
        }
        __syncthreads();
    }

    float mx = -3.402823466e38f;
    for (int i = tid; i < Ss; i += 256) mx = fmaxf(mx, lg[i]);
#pragma unroll
    for (int o = 16; o; o >>= 1) mx = fmaxf(mx, __shfl_xor_sync(0xffffffffu, mx, o));
    if (lane == 0) red[warp] = mx;
    __syncthreads();
    mx = red[0];
#pragma unroll
    for (int w2i = 1; w2i < 8; ++w2i) mx = fmaxf(mx, red[w2i]);
    __syncthreads();

    float sum = 0.f;
    for (int i = tid; i < Ss; i += 256) {
        float e = __expf(lg[i] - mx);
        lg[i] = e;
        sum += e;
    }
#pragma unroll
    for (int o = 16; o; o >>= 1) sum += __shfl_xor_sync(0xffffffffu, sum, o);
    if (lane == 0) red[warp] = sum;
    __syncthreads();
    sum = 0.f;
#pragma unroll
    for (int w2i = 0; w2i < 8; ++w2i) sum += red[w2i];
    float inv = 1.0f / sum;

    float* orow = g_probs + (size_t)bs * Ss;
    for (int i = tid; i < Ss; i += 256) orow[i] = lg[i] * inv;
}

// ====== tf32 GEMM: 128x96 tile, 512 thr (16 warps), warp tile 32x24, 2-deep pipeline ======
// warps: wm = warp&3 (4 x 32 rows), wn = warp>>2 (4 x 24 cols); per warp 2 mt x 3 nt.
// MODE 0: ctx = probs @ H_i (per b); epilogue also writes ctxh = ctx * Hj
// MODE 1: hid = relu([ctx|Hj|ctxh] @ Wv1 + bv1)
// MODE 2: out = alpha * (hid @ Wv2 + bv2)
template <int MODE>
__global__ __launch_bounds__(512) void gemm_mma(const float* __restrict__ Ap,
                                                const float* __restrict__ Bp,
                                                const float* __restrict__ Hjp,
                                                const float* __restrict__ bias,
                                                const float* __restrict__ alpha,
                                                float* __restrict__ Cp, int Kdim, int lda) {
    const int m0 = blockIdx.x * 128;
    const int n0 = blockIdx.y * 96;
    const float* A = Ap;
    const float* Bm = Bp;
    float* C = Cp;
    size_t rowbase = 0;
    if (MODE == 0) {
        int b = blockIdx.z;
        A += (size_t)b * Ss * Ss;
        Bm += (size_t)b * Ss * Hh;
        C += (size_t)b * Ss * Hh;
        rowbase = (size_t)b * Ss;
    }

    __shared__ unsigned As[2][128][20];    // A-frag (20g + t4) mod 32 distinct
    __shared__ unsigned Bs[2][16][104];    // B-frag (104*t4 + g) mod 32 = 8t4+g distinct

    const int tid  = threadIdx.x;
    const int warp = tid >> 5, lane = tid & 31;
    const int g  = lane >> 2, t4 = lane & 3;
    const int wm = warp & 3;   // m offset wm*32
    const int wn = warp >> 2;  // n offset wn*24

    // A: 512 threads x 1 float4 = 128 rows x 16 k
    const int ar = tid >> 2, ac = (tid & 3) * 4;
    // B: 16 x 96 = 384 float4, threads 0..383
    const bool bload = (tid < 384);
    const int b0r = tid / 24, b0c = (tid % 24) * 4;

    float acc[2][3][4];
#pragma unroll
    for (int mt = 0; mt < 2; ++mt)
#pragma unroll
        for (int nt = 0; nt < 3; ++nt)
#pragma unroll
            for (int v = 0; v < 4; ++v) acc[mt][nt][v] = 0.f;

    const int nkt = Kdim / 16;   // 64 / 144 / 48 — always even

    float4 aS0, bS0, aS1, bS1;

    auto loadABv = [&](float4& qa, float4& qb, int k0) {
        int kc = k0 + ac;
        if (MODE == 1) {
            int seg = kc / Hh;   // slab-uniform (Hh % 16 == 0)
            const float* base = (seg == 0) ? g_ctx : (seg == 1) ? Hjp : g_ctxh;
            int kq = kc - seg * Hh;
            qa = *(const float4*)(base + (size_t)(m0 + ar) * Hh + kq);
        } else {
            qa = *(const float4*)(A + (size_t)(m0 + ar) * lda + kc);
        }
        if (bload) qb = *(const float4*)(Bm + (size_t)(k0 + b0r) * Hh + n0 + b0c);
    };

    auto storeABv = [&](const float4& qa, const float4& qb, int buf) {
        As[buf][ar][ac]     = tf32r(qa.x);
        As[buf][ar][ac + 1] = tf32r(qa.y);
        As[buf][ar][ac + 2] = tf32r(qa.z);
        As[buf][ar][ac + 3] = tf32r(qa.w);
        if (bload) {
            Bs[buf][b0r][b0c]     = tf32r(qb.x);
            Bs[buf][b0r][b0c + 1] = tf32r(qb.y);
            Bs[buf][b0r][b0c + 2] = tf32r(qb.z);
            Bs[buf][b0r][b0c + 3] = tf32r(qb.w);
        }
    };

    auto mmaStep = [&](int cur) {
#pragma unroll
        for (int k8 = 0; k8 < 16; k8 += 8) {
            unsigned afr[2][4], bfr[3][2];
#pragma unroll
            for (int mt = 0; mt < 2; ++mt) {
                int rb = wm * 32 + mt * 16 + g;
                afr[mt][0] = As[cur][rb][k8 + t4];
                afr[mt][1] = As[cur][rb + 8][k8 + t4];
                afr[mt][2] = As[cur][rb][k8 + t4 + 4];
                afr[mt][3] = As[cur][rb + 8][k8 + t4 + 4];
            }
#pragma unroll
            for (int nt = 0; nt < 3; ++nt) {
                int cb = wn * 24 + nt * 8 + g;
                bfr[nt][0] = Bs[cur][k8 + t4][cb];
                bfr[nt][1] = Bs[cur][k8 + t4 + 4][cb];
            }
#pragma unroll
            for (int mt = 0; mt < 2; ++mt)
#pragma unroll
                for (int nt = 0; nt < 3; ++nt)
                    mma_tf32(acc[mt][nt][0], acc[mt][nt][1], acc[mt][nt][2], acc[mt][nt][3],
                             afr[mt][0], afr[mt][1], afr[mt][2], afr[mt][3],
                             bfr[nt][0], bfr[nt][1]);
        }
    };

    // prologue: slab0 -> set0 -> buf0; slab1 -> set1 (stored at iter 0)
    loadABv(aS0, bS0, 0);
    loadABv(aS1, bS1, 16);
    storeABv(aS0, bS0, 0);
    __syncthreads();

#pragma unroll 1
    for (int kt = 0; kt < nkt; kt += 2) {
        if (kt + 1 < nkt) storeABv(aS1, bS1, 1);
        if (kt + 2 < nkt) loadABv(aS0, bS0, (kt + 2) * 16);
        mmaStep(0);
        if (kt + 1 < nkt) __syncthreads();
        if (kt + 1 < nkt) {
            if (kt + 2 < nkt) storeABv(aS0, bS0, 0);
            if (kt + 3 < nkt) loadABv(aS1, bS1, (kt + 3) * 16);
            mmaStep(1);
            if (kt + 2 < nkt) __syncthreads();
        }
    }

    // ---------------- epilogue ----------------
    const float al = (MODE == 2) ? alpha[0] : 0.f;
#pragma unroll
    for (int mt = 0; mt < 2; ++mt) {
        int r0 = m0 + wm * 32 + mt * 16 + g;
        int r1 = r0 + 8;
#pragma unroll
        for (int nt = 0; nt < 3; ++nt) {
            int c0 = n0 + wn * 24 + nt * 8 + 2 * t4;
            float v00 = acc[mt][nt][0], v01 = acc[mt][nt][1];
            float v10 = acc[mt][nt][2], v11 = acc[mt][nt][3];
            if (MODE == 0) {
                *(float2*)(&C[(size_t)r0 * Hh + c0]) = make_float2(v00, v01);
                *(float2*)(&C[(size_t)r1 * Hh + c0]) = make_float2(v10, v11);
                size_t g0 = rowbase + r0, g1 = rowbase + r1;
                float2 h0 = *(const float2*)(Hjp + g0 * Hh + c0);
                float2 h1 = *(const float2*)(Hjp + g1 * Hh + c0);
                *(float2*)(&g_ctxh[g0 * Hh + c0]) = make_float2(v00 * h0.x, v01 * h0.y);
                *(float2*)(&g_ctxh[g1 * Hh + c0]) = make_float2(v10 * h1.x, v11 * h1.y);
            } else if (MODE == 1) {
                float2 bsv = *(const float2*)(&bias[c0]);
                *(float2*)(&C[(size_t)r0 * VHID + c0]) =
                    make_float2(fmaxf(v00 + bsv.x, 0.f), fmaxf(v01 + bsv.y, 0.f));
                *(float2*)(&C[(size_t)r1 * VHID + c0]) =
                    make_float2(fmaxf(v10 + bsv.x, 0.f), fmaxf(v11 + bsv.y, 0.f));
            } else {
                float2 bsv = *(const float2*)(&bias[c0]);
                *(float2*)(&C[(size_t)r0 * Hh + c0]) =
                    make_float2(al * (v00 + bsv.x), al * (v01 + bsv.y));
                *(float2*)(&C[(size_t)r1 * Hh + c0]) =
                    make_float2(al * (v10 + bsv.x), al * (v11 + bsv.y));
            }
        }
    }
}

// ================= launch =================
extern "C" void kernel_launch(void* const* d_in, const int* in_sizes, int n_in, void* d_out,
                              int out_size) {
    const float* Hj   = (const float*)d_in[0];
    const float* Hi   = (const float*)d_in[1];
    const float* mask = (const float*)d_in[2];
    const float* Wpj  = (const float*)d_in[3];
    const float* Wpi  = (const float*)d_in[4];
    const float* W1   = (const float*)d_in[5];
    const float* b1   = (const float*)d_in[6];
    const float* W2   = (const float*)d_in[7];
    // d_in[8] = b2: constant logit shift -> cancels in softmax
    const float* Wv1   = (const float*)d_in[9];
    const float* bv1   = (const float*)d_in[10];
    const float* Wv2   = (const float*)d_in[11];
    const float* bv2   = (const float*)d_in[12];
    const float* alpha = (const float*)d_in[13];
    float* out = (float*)d_out;

    float* d_probs = nullptr;
    float* d_ctx = nullptr;
    float* d_hid = nullptr;
    cudaGetSymbolAddress((void**)&d_probs, g_probs);
    cudaGetSymbolAddress((void**)&d_ctx, g_ctx);
    cudaGetSymbolAddress((void**)&d_hid, g_hid);

    k1_prep<<<Bb * Ss, 128>>>(Hj, Hi, Wpj, Wpi, W1, b1);
    k2_mma<<<Bb * Ss, 256>>>(W1, W2, mask);
    gemm_mma<0><<<dim3(Ss / 128, Hh / 96, Bb), 512>>>(d_probs, Hi, Hj, nullptr, nullptr,
                                                      d_ctx, Ss, Ss);
    gemm_mma<1><<<dim3(Bb * Ss / 128, VHID / 96), 512>>>(nullptr, Wv1, Hj, bv1, nullptr, d_hid,
                                                         VIN, 0);
    gemm_mma<2><<<dim3(Bb * Ss / 128, Hh / 96), 512>>>(d_hid, Wv2, nullptr, bv2, alpha, out,
                                                       VHID, VHID);
}